// round 2
// baseline (speedup 1.0000x reference)
#include <cuda_runtime.h>
#include <cstdint>

// Problem constants
#define BB 8
#define DD 64
#define TT 8192
#define KK 1024
#define NROWS (BB*TT)          // 65536 vectors
#define NZ (BB*DD*TT)          // 4194304 elements of z / z_q
#define THREADS 128
#define NBLOCKS (NROWS/THREADS) // 512
#define CK 64                  // codes per smem chunk

// Scratch (no allocations allowed)
__device__ float g_wnorm[KK];
__device__ float g_partial[NBLOCKS];

// ---- packed f32x2 helpers (sm_103a FFMA2 path; ptxas will not auto-fuse) ----
__device__ __forceinline__ unsigned long long pk2(float lo, float hi) {
    unsigned long long r;
    asm("mov.b64 %0, {%1, %2};" : "=l"(r) : "f"(lo), "f"(hi));
    return r;
}
__device__ __forceinline__ void unpk2(unsigned long long v, float& lo, float& hi) {
    asm("mov.b64 {%0, %1}, %2;" : "=f"(lo), "=f"(hi) : "l"(v));
}
__device__ __forceinline__ unsigned long long fma2(unsigned long long a, unsigned long long b, unsigned long long c) {
    unsigned long long d;
    asm("fma.rn.f32x2 %0, %1, %2, %3;" : "=l"(d) : "l"(a), "l"(b), "l"(c));
    return d;
}
__device__ __forceinline__ unsigned long long mul2(unsigned long long a, unsigned long long b) {
    unsigned long long d;
    asm("mul.rn.f32x2 %0, %1, %2;" : "=l"(d) : "l"(a), "l"(b));
    return d;
}
__device__ __forceinline__ unsigned long long add2(unsigned long long a, unsigned long long b) {
    unsigned long long d;
    asm("add.rn.f32x2 %0, %1, %2;" : "=l"(d) : "l"(a), "l"(b));
    return d;
}

// ---- prep: codebook row norms ||W_k||^2 (tree-sum, deterministic) ----
__global__ void vq_prep_kernel(const float* __restrict__ W) {
    int k = blockIdx.x * blockDim.x + threadIdx.x;
    if (k >= KK) return;
    const float4* wr = reinterpret_cast<const float4*>(W + (size_t)k * DD);
    float sq[64];
#pragma unroll
    for (int j = 0; j < 16; j++) {
        float4 v = wr[j];
        sq[4*j + 0] = __fmul_rn(v.x, v.x);
        sq[4*j + 1] = __fmul_rn(v.y, v.y);
        sq[4*j + 2] = __fmul_rn(v.z, v.z);
        sq[4*j + 3] = __fmul_rn(v.w, v.w);
    }
#pragma unroll
    for (int off = 32; off >= 1; off >>= 1) {
#pragma unroll
        for (int j = 0; j < 32; j++) {
            if (j < off) sq[j] = __fadd_rn(sq[j], sq[j + off]);
        }
    }
    g_wnorm[k] = sq[0];
}

// ---- main: distances + argmin + gather z_q + per-block loss partials ----
__global__ __launch_bounds__(THREADS)
void vq_main_kernel(const float* __restrict__ z,
                    const float* __restrict__ W,
                    float* __restrict__ out_zq,
                    float* __restrict__ out_codes) {
    __shared__ __align__(16) float sW[CK * DD];   // 16 KB codebook chunk
    __shared__ float sWn[CK];
    __shared__ float sRed[THREADS];

    const int tid = threadIdx.x;
    const int row = blockIdx.x * THREADS + tid;
    const int b = row >> 13;        // / TT
    const int t = row & (TT - 1);
    const float* zp = z + (size_t)b * DD * TT + t;

    // Load z row (strided by TT; coalesced across the warp), pack into f32x2,
    // and build ||z||^2 with a binary-tree reduction.
    unsigned long long zz[32];
    float sq[32];
#pragma unroll
    for (int j = 0; j < 32; j++) {
        float v0 = zp[(size_t)(2*j)     * TT];
        float v1 = zp[(size_t)(2*j + 1) * TT];
        zz[j] = pk2(v0, v1);
        sq[j] = __fadd_rn(__fmul_rn(v0, v0), __fmul_rn(v1, v1));
    }
#pragma unroll
    for (int off = 16; off >= 1; off >>= 1) {
#pragma unroll
        for (int j = 0; j < 16; j++) {
            if (j < off) sq[j] = __fadd_rn(sq[j], sq[j + off]);
        }
    }
    const float znorm = sq[0];

    float dmin = 3.4e38f;
    int imin = 0;

    for (int c0 = 0; c0 < KK; c0 += CK) {
        __syncthreads();
        // cooperative chunk load: CK*DD/4 = 1024 float4, 8 per thread
        {
            const float4* src = reinterpret_cast<const float4*>(W + (size_t)c0 * DD);
            float4* dst = reinterpret_cast<float4*>(sW);
#pragma unroll
            for (int i = 0; i < (CK * DD / 4) / THREADS; i++)
                dst[tid + i * THREADS] = src[tid + i * THREADS];
            if (tid < CK) sWn[tid] = g_wnorm[c0 + tid];
        }
        __syncthreads();

        for (int k = 0; k < CK; k++) {
            const ulonglong2* wq = reinterpret_cast<const ulonglong2*>(sW + k * DD);
            ulonglong2 w0 = wq[0];
            ulonglong2 w1 = wq[1];
            unsigned long long a0 = mul2(zz[0], w0.x);
            unsigned long long a1 = mul2(zz[1], w0.y);
            unsigned long long a2 = mul2(zz[2], w1.x);
            unsigned long long a3 = mul2(zz[3], w1.y);
#pragma unroll
            for (int j = 2; j < 16; j += 2) {
                ulonglong2 wa = wq[j];
                ulonglong2 wb = wq[j + 1];
                a0 = fma2(zz[2*j + 0], wa.x, a0);
                a1 = fma2(zz[2*j + 1], wa.y, a1);
                a2 = fma2(zz[2*j + 2], wb.x, a2);
                a3 = fma2(zz[2*j + 3], wb.y, a3);
            }
            a0 = add2(a0, a2);
            a1 = add2(a1, a3);
            a0 = add2(a0, a1);
            float slo, shi;
            unpk2(a0, slo, shi);
            float s = __fadd_rn(slo, shi);
            // distances = (||z||^2 - 2*s) + ||w||^2, rounded per-op like the ref
            float dist = __fadd_rn(__fsub_rn(znorm, __fmul_rn(2.0f, s)), sWn[k]);
            if (dist < dmin) { dmin = dist; imin = c0 + k; }   // first-index wins on ties
        }
    }

    // codes (as float; values 0..1023 exact)
    out_codes[row] = (float)imin;

    // gather winning codebook row -> z_q (layout [B, D, T]) + loss partial
    const float4* wrow = reinterpret_cast<const float4*>(W + (size_t)imin * DD);
    float* oz = out_zq + (size_t)b * DD * TT + t;
    float lsum = 0.0f;
#pragma unroll
    for (int j = 0; j < 16; j++) {
        float4 wv = wrow[j];
        int d = 4 * j;
        float z0, z1, z2, z3;
        unpk2(zz[2*j],     z0, z1);
        unpk2(zz[2*j + 1], z2, z3);
        oz[(size_t)(d + 0) * TT] = wv.x;
        oz[(size_t)(d + 1) * TT] = wv.y;
        oz[(size_t)(d + 2) * TT] = wv.z;
        oz[(size_t)(d + 3) * TT] = wv.w;
        float e0 = wv.x - z0, e1 = wv.y - z1, e2 = wv.z - z2, e3 = wv.w - z3;
        lsum += e0 * e0 + e1 * e1 + e2 * e2 + e3 * e3;
    }

    // deterministic block reduction of loss partials
    sRed[tid] = lsum;
    __syncthreads();
#pragma unroll
    for (int s = THREADS / 2; s > 0; s >>= 1) {
        if (tid < s) sRed[tid] += sRed[tid + s];
        __syncthreads();
    }
    if (tid == 0) g_partial[blockIdx.x] = sRed[0];
}

// ---- finalize: vq_loss = 1.25 * mean((z_q - z)^2) ----
__global__ void vq_finalize_kernel(float* __restrict__ out_loss) {
    __shared__ float sRed[256];
    int tid = threadIdx.x;
    sRed[tid] = g_partial[tid] + g_partial[tid + 256];
    __syncthreads();
#pragma unroll
    for (int s = 128; s > 0; s >>= 1) {
        if (tid < s) sRed[tid] += sRed[tid + s];
        __syncthreads();
    }
    if (tid == 0) out_loss[0] = 1.25f * (sRed[0] / (float)NZ);
}

extern "C" void kernel_launch(void* const* d_in, const int* in_sizes, int n_in,
                              void* d_out, int out_size) {
    const float* z = (const float*)d_in[0];         // [8, 64, 8192]
    const float* W = (const float*)d_in[1];         // [1024, 64]
    float* out = (float*)d_out;
    // Layout: [z_q_st (NZ)] [vq_loss (1)] [codes (NROWS)]
    float* out_zq    = out;
    float* out_loss  = out + NZ;
    float* out_codes = out + NZ + 1;

    vq_prep_kernel<<<8, 128>>>(W);
    vq_main_kernel<<<NBLOCKS, THREADS>>>(z, W, out_zq, out_codes);
    vq_finalize_kernel<<<1, 256>>>(out_loss);
}